// round 6
// baseline (speedup 1.0000x reference)
#include <cuda_runtime.h>
#include <cuda_fp16.h>
#include <cuda_pipeline.h>
#include <mma.h>

using namespace nvcuda;

#define T_TOK 512
#define H_DIM 4096
#define F_DIM 14336
#define GROUP 64
#define KC 64            // K chunk per pipeline stage == GROUP
#define NT 64            // N tile per CTA
#define THREADS 512
#define WARPS_M 8
#define WARPS_N 2
#define A_STRIDE 80      // halves; 160B row, 32B-aligned rows
#define BQ_STRIDE 68     // ints;   272B row, 16B-aligned rows
#define BH_STRIDE 80     // halves
#define CT_STRIDE 72     // floats; 288B row, 32B-aligned rows

// -------- scratch (static device globals; no allocation) --------
__device__ __half g_Xh[(size_t)T_TOK * H_DIM];          // 4 MB
__device__ float  g_H1[(size_t)T_TOK * F_DIM];          // 29.4 MB
__device__ __half g_ACT[(size_t)T_TOK * F_DIM];         // 14.7 MB

// -------- X fp32 -> fp16 --------
__global__ void convert_x_kernel(const float* __restrict__ x) {
    int i = blockIdx.x * blockDim.x + threadIdx.x;
    if (i < T_TOK * H_DIM) g_Xh[i] = __float2half(x[i]);
}

// -------- fused dequant-GEMM --------
// C[m, n] = sum_k A[m, k] * dequant(Wq[n, k])
// MODE 0: store fp32 to C (ldc)
// MODE 1: act = silu(H1gate[tile]) * c ; store fp16 to ActOut  (C unused)
template<int M_TILE, int MODE>
__launch_bounds__(THREADS, 1)
__global__ void gemm_dq(const __half* __restrict__ A, int K,
                        const int* __restrict__ Wq,
                        const float* __restrict__ scale,
                        const float* __restrict__ zero,
                        float* __restrict__ C, int ldc,
                        const float* __restrict__ H1gate,
                        __half* __restrict__ ActOut)
{
    constexpr int WM = M_TILE / WARPS_M;      // 64 (M=512) or 32 (M=256)
    constexpr int MF = WM / 16;               // 4 or 2
    constexpr int WN = NT / WARPS_N;          // 32
    constexpr int NF = WN / 16;               // 2

    extern __shared__ __align__(32) char smem[];
    __half* sA  = (__half*)smem;                                        // 2 * M_TILE * A_STRIDE halves
    int*    sBq = (int*)(smem + (size_t)2 * M_TILE * A_STRIDE * 2);     // 2 * NT * BQ_STRIDE ints
    float*  sSc = (float*)((char*)sBq + (size_t)2 * NT * BQ_STRIDE * 4);
    float*  sZr = sSc + 2 * NT;
    __half* sBh = (__half*)(sZr + 2 * NT);                              // NT * BH_STRIDE halves

    const int tid = threadIdx.x;
    const int n0 = blockIdx.x * NT;
    const int m0 = blockIdx.y * M_TILE;
    const int ksz = K / GROUP;
    const int NIT = K / KC;

    auto prefetch = [&](int buf, int it) {
        const int k0 = it * KC;
        // A tile: M_TILE rows x (KC halves = 8 x 16B segments)
        #pragma unroll
        for (int r = 0; r < (M_TILE * 8) / THREADS; r++) {
            int idx = r * THREADS + tid;
            int row = idx >> 3, seg = idx & 7;
            __pipeline_memcpy_async(
                sA + (size_t)buf * M_TILE * A_STRIDE + row * A_STRIDE + seg * 8,
                A + (size_t)(m0 + row) * K + k0 + seg * 8, 16);
        }
        // Bq tile: NT rows x (KC ints = 16 x 16B segments)
        #pragma unroll
        for (int r = 0; r < (NT * 16) / THREADS; r++) {
            int idx = r * THREADS + tid;
            int row = idx >> 4, seg = idx & 15;
            __pipeline_memcpy_async(
                sBq + (size_t)buf * NT * BQ_STRIDE + row * BQ_STRIDE + seg * 4,
                Wq + (size_t)(n0 + row) * K + k0 + seg * 4, 16);
        }
        // per-row scale/zero for group g = it (KC == GROUP)
        if (tid < NT) {
            __pipeline_memcpy_async(&sSc[buf * NT + tid],
                                    &scale[(size_t)(n0 + tid) * ksz + it], 4);
        } else if (tid < 2 * NT) {
            int n = tid - NT;
            __pipeline_memcpy_async(&sZr[buf * NT + n],
                                    &zero[(size_t)(n0 + n) * ksz + it], 4);
        }
    };

    wmma::fragment<wmma::accumulator, 16, 16, 16, float> acc[MF][NF];
    #pragma unroll
    for (int i = 0; i < MF; i++)
        #pragma unroll
        for (int j = 0; j < NF; j++)
            wmma::fill_fragment(acc[i][j], 0.0f);

    const int wid = tid >> 5;
    const int wm = wid % WARPS_M;
    const int wn = wid / WARPS_M;

    prefetch(0, 0);
    __pipeline_commit();

    for (int it = 0; it < NIT; it++) {
        const int buf = it & 1;
        if (it + 1 < NIT) prefetch(buf ^ 1, it + 1);
        __pipeline_commit();               // always commit (empty group on last iter)
        __pipeline_wait_prior(1);          // current buffer's group complete
        __syncthreads();

        // dequant Bq[buf] -> Bh (fp16):  w = (q - zero) * scale
        {
            const int n = tid >> 3, kb = (tid & 7) * 8;
            const float s = sSc[buf * NT + n];
            const float z = sZr[buf * NT + n];
            const int* q = sBq + (size_t)buf * NT * BQ_STRIDE + n * BQ_STRIDE + kb;
            __half* o = sBh + n * BH_STRIDE + kb;
            #pragma unroll
            for (int i = 0; i < 8; i++)
                o[i] = __float2half(((float)q[i] - z) * s);
        }
        __syncthreads();

        // compute
        const __half* Abase = sA + (size_t)buf * M_TILE * A_STRIDE + wm * WM * A_STRIDE;
        #pragma unroll
        for (int kk = 0; kk < KC / 16; kk++) {
            wmma::fragment<wmma::matrix_b, 16, 16, 16, __half, wmma::col_major> bf[NF];
            #pragma unroll
            for (int j = 0; j < NF; j++)
                wmma::load_matrix_sync(bf[j],
                    sBh + (wn * WN + j * 16) * BH_STRIDE + kk * 16, BH_STRIDE);
            #pragma unroll
            for (int i = 0; i < MF; i++) {
                wmma::fragment<wmma::matrix_a, 16, 16, 16, __half, wmma::row_major> af;
                wmma::load_matrix_sync(af, Abase + i * 16 * A_STRIDE + kk * 16, A_STRIDE);
                #pragma unroll
                for (int j = 0; j < NF; j++)
                    wmma::mma_sync(acc[i][j], af, bf[j], acc[i][j]);
            }
        }
        __syncthreads();
    }

    if constexpr (MODE == 0) {
        #pragma unroll
        for (int i = 0; i < MF; i++)
            #pragma unroll
            for (int j = 0; j < NF; j++) {
                int mrow = m0 + wm * WM + i * 16;
                int ncol = n0 + wn * WN + j * 16;
                wmma::store_matrix_sync(C + (size_t)mrow * ldc + ncol,
                                        acc[i][j], ldc, wmma::mem_row_major);
            }
    } else {
        // stash h3 tile in smem (pipeline buffers dead), then fuse silu(h1)*h3
        float* sC = (float*)smem;
        #pragma unroll
        for (int i = 0; i < MF; i++)
            #pragma unroll
            for (int j = 0; j < NF; j++) {
                int mrow = wm * WM + i * 16;
                int ncol = wn * WN + j * 16;
                wmma::store_matrix_sync(sC + (size_t)mrow * CT_STRIDE + ncol,
                                        acc[i][j], CT_STRIDE, wmma::mem_row_major);
            }
        __syncthreads();
        #pragma unroll
        for (int l = 0; l < (M_TILE * NT) / THREADS; l++) {
            int flat = l * THREADS + tid;
            int m = flat / NT, n = flat % NT;
            float h3 = sC[(size_t)m * CT_STRIDE + n];
            float h1 = H1gate[(size_t)(m0 + m) * F_DIM + n0 + n];
            float sv = h1 / (1.0f + __expf(-h1));   // silu
            ActOut[(size_t)(m0 + m) * F_DIM + n0 + n] = __float2half(sv * h3);
        }
    }
}

static constexpr int smem_bytes(int M) {
    return 2 * M * A_STRIDE * 2        // sA
         + 2 * NT * BQ_STRIDE * 4      // sBq
         + 2 * NT * 4 * 2              // sSc + sZr
         + NT * BH_STRIDE * 2;         // sBh
}

extern "C" void kernel_launch(void* const* d_in, const int* in_sizes, int n_in,
                              void* d_out, int out_size) {
    const float* x  = (const float*)d_in[0];
    const int* W1q  = (const int*)d_in[1];
    const float* s1 = (const float*)d_in[2];
    const float* z1 = (const float*)d_in[3];
    const int* W3q  = (const int*)d_in[4];
    const float* s3 = (const float*)d_in[5];
    const float* z3 = (const float*)d_in[6];
    const int* W2q  = (const int*)d_in[7];
    const float* s2 = (const float*)d_in[8];
    const float* z2 = (const float*)d_in[9];
    float* out = (float*)d_out;

    void *pXh, *pH1, *pACT;
    cudaGetSymbolAddress(&pXh, g_Xh);
    cudaGetSymbolAddress(&pH1, g_H1);
    cudaGetSymbolAddress(&pACT, g_ACT);
    const __half* Xh = (const __half*)pXh;
    float* H1 = (float*)pH1;
    __half* ACT = (__half*)pACT;

    constexpr int SM512 = smem_bytes(512);   // 209920 B
    constexpr int SM256 = smem_bytes(256);   // 128000 B
    cudaFuncSetAttribute(gemm_dq<512, 0>, cudaFuncAttributeMaxDynamicSharedMemorySize, SM512);
    cudaFuncSetAttribute(gemm_dq<512, 1>, cudaFuncAttributeMaxDynamicSharedMemorySize, SM512);
    cudaFuncSetAttribute(gemm_dq<256, 0>, cudaFuncAttributeMaxDynamicSharedMemorySize, SM256);

    // 1) X -> fp16
    convert_x_kernel<<<(T_TOK * H_DIM + 1023) / 1024, 1024>>>(x);

    // 2) H1 = X @ W1^T   (fp32 scratch)
    dim3 g13(F_DIM / NT, 1);
    gemm_dq<512, 0><<<g13, THREADS, SM512>>>(Xh, H_DIM, W1q, s1, z1,
                                             H1, F_DIM, nullptr, nullptr);

    // 3) ACT = silu(H1) * (X @ W3^T)   (fp16)
    gemm_dq<512, 1><<<g13, THREADS, SM512>>>(Xh, H_DIM, W3q, s3, z3,
                                             nullptr, 0, H1, ACT);

    // 4) out = ACT @ W2^T   (fp32)
    dim3 g2(H_DIM / NT, 2);
    gemm_dq<256, 0><<<g2, THREADS, SM256>>>(ACT, F_DIM, W2q, s2, z2,
                                            out, H_DIM, nullptr, nullptr);
}

// round 10
// speedup vs baseline: 1.7629x; 1.7629x over previous
#include <cuda_runtime.h>
#include <cuda_fp16.h>
#include <cuda_pipeline.h>
#include <cstdint>

#define T_TOK 512
#define H_DIM 4096
#define F_DIM 14336
#define KC 64
#define NT 64
#define THREADS 512
#define SPLIT2 2

// smem: A tiles 2 x (512 x 128B) then B tiles 2 x (64 x 128B)
#define SA_BUF 65536
#define SB_OFF  (2 * SA_BUF)
#define SB_BUF  8192
#define SMEM_TOTAL (SB_OFF + 2 * SB_BUF)   // 147456

// ---- scratch ----
__device__ __half g_Xh[(size_t)T_TOK * H_DIM];
__device__ float  g_H1[(size_t)T_TOK * F_DIM];
__device__ __half g_ACT[(size_t)T_TOK * F_DIM];
__device__ float  g_P2[(size_t)SPLIT2 * T_TOK * H_DIM];

__device__ __forceinline__ uint32_t smem_to_u32(const void* p) {
    uint32_t a;
    asm("{ .reg .u64 t; cvta.to.shared.u64 t, %1; cvt.u32.u64 %0, t; }" : "=r"(a) : "l"(p));
    return a;
}
__device__ __forceinline__ void ldsm4(uint32_t* r, uint32_t addr) {
    asm volatile("ldmatrix.sync.aligned.m8n8.x4.shared.b16 {%0,%1,%2,%3}, [%4];"
                 : "=r"(r[0]), "=r"(r[1]), "=r"(r[2]), "=r"(r[3]) : "r"(addr));
}
__device__ __forceinline__ void mma16816(float* c, const uint32_t* a, const uint32_t* b) {
    asm volatile("mma.sync.aligned.m16n8k16.row.col.f32.f16.f16.f32 "
                 "{%0,%1,%2,%3}, {%4,%5,%6,%7}, {%8,%9}, {%0,%1,%2,%3};"
                 : "+f"(c[0]), "+f"(c[1]), "+f"(c[2]), "+f"(c[3])
                 : "r"(a[0]), "r"(a[1]), "r"(a[2]), "r"(a[3]), "r"(b[0]), "r"(b[1]));
}
__device__ __forceinline__ uint32_t h2u(__half2 h) { return *reinterpret_cast<uint32_t*>(&h); }

// ================= X fp32 -> fp16 =================
__global__ void convert_x_kernel(const float* __restrict__ x) {
    int i = blockIdx.x * blockDim.x + threadIdx.x;
    g_Xh[i] = __float2half(x[i]);
}

// ================= dequant-GEMM (mma.sync HMMA) =================
// C[m, n0+j] = sum_k A[m,k] * (Wq[n0+j,k] - zero)*scale
// MODE 0: -> H1 fp32 (ld F_DIM)
// MODE 1: ACT = silu(H1) * c, fp16 (ld F_DIM)
// MODE 2: partial fp32 -> outP + blockIdx.y*T*H (ld H_DIM)
template<int MODE>
__global__ __launch_bounds__(THREADS, 1)
void tc_gemm(const __half* __restrict__ A, const int* __restrict__ Wq,
             const float* __restrict__ scale, const float* __restrict__ zero,
             int K_full, int NIT,
             float* __restrict__ H1, __half* __restrict__ ACT, float* __restrict__ outP)
{
    extern __shared__ __align__(128) char smem[];
    const uint32_t sm = smem_to_u32(smem);
    const int tid = threadIdx.x;
    const int wid = tid >> 5, lane = tid & 31;
    const int wm = wid & 7, wn = wid >> 3;          // 8 M-warps x 2 N-warps
    const int n0 = blockIdx.x * NT;
    const int k_start = blockIdx.y * (NIT * KC);
    const int ksz = K_full >> 6;

    // ---- per-thread dequant task: B row nrow (0..63), segment sseg (8 ints) ----
    const int nrow = tid >> 3, sseg = tid & 7;
    const int* wrow = Wq + (size_t)(n0 + nrow) * K_full;
    const float* scp = scale + (size_t)(n0 + nrow) * ksz;
    const float* zrp = zero + (size_t)(n0 + nrow) * ksz;
    const uint32_t b_sts_off = SB_OFF + nrow * 128 + ((sseg * 16) ^ ((nrow & 7) * 16));

    int4 wq0, wq1; float scw, zrw;

#define LOADW(it_) do { int k0_ = k_start + (it_) * KC; \
    const int4* p_ = (const int4*)(wrow + k0_ + sseg * 8); \
    wq0 = p_[0]; wq1 = p_[1]; \
    int g_ = k0_ >> 6; scw = scp[g_]; zrw = zrp[g_]; } while (0)

#define LOADA(it_, buf_) do { int k0_ = k_start + (it_) * KC; \
    _Pragma("unroll") \
    for (int r_ = 0; r_ < 8; r_++) { \
        int idx_ = r_ * THREADS + tid; int row_ = idx_ >> 3, sg_ = idx_ & 7; \
        __pipeline_memcpy_async( \
            smem + (buf_) * SA_BUF + row_ * 128 + ((sg_ * 16) ^ ((row_ & 7) * 16)), \
            A + (size_t)row_ * K_full + k0_ + sg_ * 8, 16); \
    } __pipeline_commit(); } while (0)

    // ---- ldmatrix per-lane addressing ----
    // Row base pointers carry NO column component; the swizzled column offset
    // is computed per k-step:  col_k = (c0 + k*32) ^ ((lane&7)*16)  (<= 112).
    const int swz = (lane & 7) * 16;
    // A x4: lanes 0-7 rows0-7@k0, 8-15 rows8-15@k0, 16-23 rows0-7@k8, 24-31 rows8-15@k8
    const int a_row = (lane & 7) + ((lane >> 3) & 1) * 8;
    const int a_c0 = (lane >> 4) * 16;                 // bytes
    uint32_t pA[4];
    #pragma unroll
    for (int i = 0; i < 4; i++)
        pA[i] = sm + (wm * 64 + i * 16 + a_row) * 128;
    // B x4: lanes 0-7 n0-7@k0, 8-15 n0-7@k8, 16-23 n8-15@k0, 24-31 n8-15@k8
    const int b_n = (lane & 7) + (lane >> 4) * 8;
    const int b_c0 = ((lane >> 3) & 1) * 16;
    uint32_t pB[2];
    #pragma unroll
    for (int j = 0; j < 2; j++)
        pB[j] = sm + SB_OFF + (wn * 32 + j * 16 + b_n) * 128;
    // per-k swizzled column offsets
    uint32_t akoff[4], bkoff[4];
    #pragma unroll
    for (int k = 0; k < 4; k++) {
        akoff[k] = (uint32_t)((a_c0 + k * 32) ^ swz);
        bkoff[k] = (uint32_t)((b_c0 + k * 32) ^ swz);
    }

    float acc[4][4][4];
    #pragma unroll
    for (int i = 0; i < 4; i++)
        #pragma unroll
        for (int j = 0; j < 4; j++)
            acc[i][j][0] = acc[i][j][1] = acc[i][j][2] = acc[i][j][3] = 0.0f;

    LOADW(0);
    LOADA(0, 0);

    for (int it = 0; it < NIT; it++) {
        const int buf = it & 1;
        __pipeline_wait_prior(0);

        // dequant current weights -> swizzled fp16 B tile
        {
            float nz = -zrw * scw;
            __half2 v0 = __floats2half2_rn(fmaf((float)wq0.x, scw, nz), fmaf((float)wq0.y, scw, nz));
            __half2 v1 = __floats2half2_rn(fmaf((float)wq0.z, scw, nz), fmaf((float)wq0.w, scw, nz));
            __half2 v2 = __floats2half2_rn(fmaf((float)wq1.x, scw, nz), fmaf((float)wq1.y, scw, nz));
            __half2 v3 = __floats2half2_rn(fmaf((float)wq1.z, scw, nz), fmaf((float)wq1.w, scw, nz));
            uint4 v = { h2u(v0), h2u(v1), h2u(v2), h2u(v3) };
            *(uint4*)(smem + b_sts_off + buf * SB_BUF) = v;
        }
        __syncthreads();

        // prefetch next chunk BEFORE compute (latency hidden under mma)
        if (it + 1 < NIT) {
            LOADW(it + 1);
            LOADA(it + 1, buf ^ 1);
        }

        // compute: 4 k-steps x (4 m-frags x 4 n-frags)
        const uint32_t aoff = buf * SA_BUF;
        const uint32_t boff = buf * SB_BUF;
        #pragma unroll
        for (int k = 0; k < 4; k++) {
            uint32_t bfr[2][4];
            ldsm4(bfr[0], pB[0] + boff + bkoff[k]);
            ldsm4(bfr[1], pB[1] + boff + bkoff[k]);
            #pragma unroll
            for (int i = 0; i < 4; i++) {
                uint32_t afr[4];
                ldsm4(afr, pA[i] + aoff + akoff[k]);
                #pragma unroll
                for (int j = 0; j < 4; j++)
                    mma16816(acc[i][j], afr, bfr[j >> 1] + (j & 1) * 2);
            }
        }
        __syncthreads();
    }

    // ---- epilogue ----
    const int r_base = wm * 64 + (lane >> 2);
    const int c_rel = wn * 32 + (lane & 3) * 2;
    #pragma unroll
    for (int i = 0; i < 4; i++) {
        #pragma unroll
        for (int j = 0; j < 4; j++) {
            int r = r_base + i * 16;
            int c = n0 + c_rel + j * 8;
            float2 lo = { acc[i][j][0], acc[i][j][1] };
            float2 hi = { acc[i][j][2], acc[i][j][3] };
            if constexpr (MODE == 0) {
                *(float2*)(H1 + (size_t)r * F_DIM + c) = lo;
                *(float2*)(H1 + (size_t)(r + 8) * F_DIM + c) = hi;
            } else if constexpr (MODE == 1) {
                float2 g0 = *(const float2*)(H1 + (size_t)r * F_DIM + c);
                float2 g1 = *(const float2*)(H1 + (size_t)(r + 8) * F_DIM + c);
                float o0 = g0.x / (1.0f + __expf(-g0.x)) * lo.x;
                float o1 = g0.y / (1.0f + __expf(-g0.y)) * lo.y;
                float o2 = g1.x / (1.0f + __expf(-g1.x)) * hi.x;
                float o3 = g1.y / (1.0f + __expf(-g1.y)) * hi.y;
                *(__half2*)(ACT + (size_t)r * F_DIM + c) = __floats2half2_rn(o0, o1);
                *(__half2*)(ACT + (size_t)(r + 8) * F_DIM + c) = __floats2half2_rn(o2, o3);
            } else {
                float* dst = outP + (size_t)blockIdx.y * (T_TOK * H_DIM);
                *(float2*)(dst + (size_t)r * H_DIM + c) = lo;
                *(float2*)(dst + (size_t)(r + 8) * H_DIM + c) = hi;
            }
        }
    }
#undef LOADW
#undef LOADA
}

// ================= split-K reduce (2 partials) =================
__global__ void reduce2_kernel(float* __restrict__ out) {
    const size_t S = (size_t)T_TOK * H_DIM / 4;
    size_t i = (size_t)blockIdx.x * blockDim.x + threadIdx.x;
    const float4* p = (const float4*)g_P2;
    float4 a = p[i], b = p[i + S];
    float4 r = { a.x + b.x, a.y + b.y, a.z + b.z, a.w + b.w };
    ((float4*)out)[i] = r;
}

// ================= launch =================
extern "C" void kernel_launch(void* const* d_in, const int* in_sizes, int n_in,
                              void* d_out, int out_size) {
    const float* x  = (const float*)d_in[0];
    const int* W1q  = (const int*)d_in[1];
    const float* s1 = (const float*)d_in[2];
    const float* z1 = (const float*)d_in[3];
    const int* W3q  = (const int*)d_in[4];
    const float* s3 = (const float*)d_in[5];
    const float* z3 = (const float*)d_in[6];
    const int* W2q  = (const int*)d_in[7];
    const float* s2 = (const float*)d_in[8];
    const float* z2 = (const float*)d_in[9];
    float* out = (float*)d_out;

    void *pXh, *pH1, *pACT, *pP2;
    cudaGetSymbolAddress(&pXh, g_Xh);
    cudaGetSymbolAddress(&pH1, g_H1);
    cudaGetSymbolAddress(&pACT, g_ACT);
    cudaGetSymbolAddress(&pP2, g_P2);
    const __half* Xh = (const __half*)pXh;
    float* H1 = (float*)pH1;
    __half* ACT = (__half*)pACT;
    float* P2 = (float*)pP2;

    cudaFuncSetAttribute(tc_gemm<0>, cudaFuncAttributeMaxDynamicSharedMemorySize, SMEM_TOTAL);
    cudaFuncSetAttribute(tc_gemm<1>, cudaFuncAttributeMaxDynamicSharedMemorySize, SMEM_TOTAL);
    cudaFuncSetAttribute(tc_gemm<2>, cudaFuncAttributeMaxDynamicSharedMemorySize, SMEM_TOTAL);

    convert_x_kernel<<<(T_TOK * H_DIM) / 1024, 1024>>>(x);

    // GEMM1: H1 = X @ W1^T   (grid 224)
    tc_gemm<0><<<F_DIM / NT, THREADS, SMEM_TOTAL>>>(Xh, W1q, s1, z1, H_DIM, H_DIM / KC,
                                                    H1, nullptr, nullptr);
    // GEMM3 fused silu-mul -> ACT (grid 224)
    tc_gemm<1><<<F_DIM / NT, THREADS, SMEM_TOTAL>>>(Xh, W3q, s3, z3, H_DIM, H_DIM / KC,
                                                    H1, ACT, nullptr);
    // GEMM2 split-K=2 (grid 64 x 2)
    dim3 g2(H_DIM / NT, SPLIT2);
    tc_gemm<2><<<g2, THREADS, SMEM_TOTAL>>>(ACT, W2q, s2, z2, F_DIM, F_DIM / (KC * SPLIT2),
                                            nullptr, nullptr, P2);
    // reduce -> out
    reduce2_kernel<<<(T_TOK * H_DIM / 4) / 256, 256>>>(out);
}

// round 12
// speedup vs baseline: 2.3452x; 1.3303x over previous
#include <cuda_runtime.h>
#include <cuda_fp16.h>
#include <cuda_pipeline.h>
#include <cstdint>

#define T_TOK 512
#define H_DIM 4096
#define F_DIM 14336
#define KC 64
#define THREADS 256
#define M_TILE 256
#define SPLIT 7

// smem: A 3 stages x (256 x 128B), B 2 bufs x (128 x 128B)
#define SA_STAGE 32768
#define SB_OFF   (3 * SA_STAGE)          // 98304
#define SB_BUF   16384
#define SMEM_TOTAL (SB_OFF + 2 * SB_BUF) // 131072

// ---- scratch ----
__device__ __half g_Xh[(size_t)T_TOK * H_DIM];
__device__ __half g_ACT[(size_t)T_TOK * F_DIM];
__device__ float  g_P2[(size_t)SPLIT * T_TOK * H_DIM];

__device__ __forceinline__ uint32_t smem_to_u32(const void* p) {
    uint32_t a;
    asm("{ .reg .u64 t; cvta.to.shared.u64 t, %1; cvt.u32.u64 %0, t; }" : "=r"(a) : "l"(p));
    return a;
}
__device__ __forceinline__ void ldsm4(uint32_t* r, uint32_t addr) {
    asm volatile("ldmatrix.sync.aligned.m8n8.x4.shared.b16 {%0,%1,%2,%3}, [%4];"
                 : "=r"(r[0]), "=r"(r[1]), "=r"(r[2]), "=r"(r[3]) : "r"(addr));
}
__device__ __forceinline__ void mma16816(float* c, const uint32_t* a, const uint32_t* b) {
    asm volatile("mma.sync.aligned.m16n8k16.row.col.f32.f16.f16.f32 "
                 "{%0,%1,%2,%3}, {%4,%5,%6,%7}, {%8,%9}, {%0,%1,%2,%3};"
                 : "+f"(c[0]), "+f"(c[1]), "+f"(c[2]), "+f"(c[3])
                 : "r"(a[0]), "r"(a[1]), "r"(a[2]), "r"(a[3]), "r"(b[0]), "r"(b[1]));
}
__device__ __forceinline__ uint32_t h2u(__half2 h) { return *reinterpret_cast<uint32_t*>(&h); }

// ================= X fp32 -> fp16 =================
__global__ void convert_x_kernel(const float* __restrict__ x) {
    int i = blockIdx.x * blockDim.x + threadIdx.x;
    g_Xh[i] = __float2half(x[i]);
}

// ================= dequant-GEMM (mma.sync HMMA) =================
// MODE 0 (fused G1+G3): B rows 0-63 = W1 cols n0..n0+63, rows 64-127 = W3 same cols.
//   epilogue: ACT = silu(X@W1^T) * (X@W3^T), fp16.
// MODE 1 (G2): B rows 0-127 = W2 cols n0..n0+127; partial fp32 -> outP + sp*T*H.
template<int MODE>
__global__ __launch_bounds__(THREADS, 1)
void tc_gemm(const __half* __restrict__ A,
             const int* __restrict__ Wqa, const int* __restrict__ Wqb,
             const float* __restrict__ sca, const float* __restrict__ zra,
             const float* __restrict__ scb, const float* __restrict__ zrb,
             int K_full, int NIT,
             __half* __restrict__ ACT, float* __restrict__ outP)
{
    extern __shared__ __align__(128) char smem[];
    const uint32_t sm = smem_to_u32(smem);
    const int tid = threadIdx.x;
    const int wid = tid >> 5, lane = tid & 31;
    const int wm = wid & 3, wn = wid >> 2;     // 4 M-warps x 2 N-warps
    int n0, m0, k_start, sp;
    if (MODE == 0) {
        m0 = blockIdx.x * M_TILE;              // gridDim.x = 2 (m fastest: L2 weight share)
        n0 = blockIdx.y * 64;                  // gridDim.y = 224
        k_start = 0; sp = 0;
    } else {
        int mt = blockIdx.x & 1; sp = blockIdx.x >> 1;   // gridDim.x = 14
        m0 = mt * M_TILE;
        n0 = blockIdx.y * 128;                 // gridDim.y = 32
        k_start = sp * (NIT * KC);
    }
    const int ksz = K_full >> 6;

    // ---- 4 dequant tasks per thread: B row brow (0..127), segment seg (8 ints) ----
    const int* wp[4]; const float* scp[4]; const float* zrp[4]; uint32_t sts[4];
    #pragma unroll
    for (int i = 0; i < 4; i++) {
        int t = i * THREADS + tid;
        int brow = t >> 3, seg = t & 7;
        const int* base = (MODE == 0 && i >= 2) ? Wqb : Wqa;
        const float* sc_ = (MODE == 0 && i >= 2) ? scb : sca;
        const float* zr_ = (MODE == 0 && i >= 2) ? zrb : zra;
        int grow = n0 + ((MODE == 0) ? (brow & 63) : brow);
        wp[i]  = base + (size_t)grow * K_full + seg * 8;
        scp[i] = sc_ + (size_t)grow * ksz;
        zrp[i] = zr_ + (size_t)grow * ksz;
        sts[i] = SB_OFF + brow * 128 + ((seg * 16) ^ ((brow & 7) * 16));
    }
    int4 wq[4][2]; float scw[4], zrw[4];

#define LOADW(it_) do { int k0_ = k_start + (it_) * KC; int g_ = k0_ >> 6; \
    _Pragma("unroll") \
    for (int i_ = 0; i_ < 4; i_++) { \
        const int4* p_ = (const int4*)(wp[i_] + k0_); \
        wq[i_][0] = p_[0]; wq[i_][1] = p_[1]; \
        scw[i_] = scp[i_][g_]; zrw[i_] = zrp[i_][g_]; \
    } } while (0)

#define LOADA(it_, st_) do { int k0_ = k_start + (it_) * KC; \
    _Pragma("unroll") \
    for (int r_ = 0; r_ < 8; r_++) { \
        int idx_ = r_ * THREADS + tid; int row_ = idx_ >> 3, sg_ = idx_ & 7; \
        __pipeline_memcpy_async( \
            smem + (st_) * SA_STAGE + row_ * 128 + ((sg_ * 16) ^ ((row_ & 7) * 16)), \
            A + (size_t)(m0 + row_) * K_full + k0_ + sg_ * 8, 16); \
    } } while (0)

    // ---- ldmatrix addressing (swizzle applied per k-step) ----
    const int swz = (lane & 7) * 16;
    const int a_row = (lane & 7) + ((lane >> 3) & 1) * 8;
    const int a_c0 = (lane >> 4) * 16;
    uint32_t pA[4];
    #pragma unroll
    for (int i = 0; i < 4; i++)
        pA[i] = sm + (wm * 64 + i * 16 + a_row) * 128;
    const int b_n = (lane & 7) + (lane >> 4) * 8;
    const int b_c0 = ((lane >> 3) & 1) * 16;
    uint32_t pBr[4];
    #pragma unroll
    for (int jj = 0; jj < 4; jj++) {
        int row = (MODE == 0) ? ((jj >> 1) * 64 + wn * 32 + (jj & 1) * 16 + b_n)
                              : (wn * 64 + jj * 16 + b_n);
        pBr[jj] = sm + SB_OFF + row * 128;
    }
    uint32_t akoff[4], bkoff[4];
    #pragma unroll
    for (int k = 0; k < 4; k++) {
        akoff[k] = (uint32_t)((a_c0 + k * 32) ^ swz);
        bkoff[k] = (uint32_t)((b_c0 + k * 32) ^ swz);
    }

    float acc[4][8][4];
    #pragma unroll
    for (int i = 0; i < 4; i++)
        #pragma unroll
        for (int j = 0; j < 8; j++)
            acc[i][j][0] = acc[i][j][1] = acc[i][j][2] = acc[i][j][3] = 0.0f;

    LOADW(0);
    LOADA(0, 0); __pipeline_commit();
    LOADA(1, 1); __pipeline_commit();
    int s_cur = 0, s_pre = 2;

    for (int it = 0; it < NIT; it++) {
        const int buf = it & 1;
        __pipeline_wait_prior(1);          // A[s_cur] complete

        // dequant 4 tasks -> swizzled fp16 B tile
        #pragma unroll
        for (int i = 0; i < 4; i++) {
            float nz = -zrw[i] * scw[i];
            __half2 v0 = __floats2half2_rn(fmaf((float)wq[i][0].x, scw[i], nz), fmaf((float)wq[i][0].y, scw[i], nz));
            __half2 v1 = __floats2half2_rn(fmaf((float)wq[i][0].z, scw[i], nz), fmaf((float)wq[i][0].w, scw[i], nz));
            __half2 v2 = __floats2half2_rn(fmaf((float)wq[i][1].x, scw[i], nz), fmaf((float)wq[i][1].y, scw[i], nz));
            __half2 v3 = __floats2half2_rn(fmaf((float)wq[i][1].z, scw[i], nz), fmaf((float)wq[i][1].w, scw[i], nz));
            uint4 v = { h2u(v0), h2u(v1), h2u(v2), h2u(v3) };
            *(uint4*)(smem + sts[i] + buf * SB_BUF) = v;
        }
        __syncthreads();                   // single barrier per chunk

        // prefetch next weights + A stage (latency hidden under compute)
        if (it + 1 < NIT) LOADW(it + 1);
        if (it + 2 < NIT) LOADA(it + 2, s_pre);
        __pipeline_commit();

        // compute: 4 k-steps x (4 M x 8 N) = 128 mma, 32 ldsm
        const uint32_t aoff = s_cur * SA_STAGE;
        const uint32_t boff = buf * SB_BUF;
        #pragma unroll
        for (int k = 0; k < 4; k++) {
            uint32_t bfr[4][4];
            #pragma unroll
            for (int jj = 0; jj < 4; jj++)
                ldsm4(bfr[jj], pBr[jj] + boff + bkoff[k]);
            uint32_t afr[2][4];
            ldsm4(afr[0], pA[0] + aoff + akoff[k]);
            #pragma unroll
            for (int i = 0; i < 4; i++) {
                if (i < 3) ldsm4(afr[(i + 1) & 1], pA[i + 1] + aoff + akoff[k]);
                #pragma unroll
                for (int j = 0; j < 8; j++)
                    mma16816(acc[i][j], afr[i & 1], bfr[j >> 1] + (j & 1) * 2);
            }
        }
        s_cur = (s_cur == 2) ? 0 : s_cur + 1;
        s_pre = (s_pre == 2) ? 0 : s_pre + 1;
    }

    // ---- epilogue ----
    const int r0 = m0 + wm * 64 + (lane >> 2);
    if constexpr (MODE == 0) {
        #pragma unroll
        for (int i = 0; i < 4; i++) {
            #pragma unroll
            for (int j = 0; j < 4; j++) {
                int r = r0 + i * 16;
                int c = n0 + wn * 32 + j * 8 + (lane & 3) * 2;
                float h1a = acc[i][j][0], h1b = acc[i][j][1];
                float h1c = acc[i][j][2], h1d = acc[i][j][3];
                float o0 = h1a / (1.0f + __expf(-h1a)) * acc[i][j + 4][0];
                float o1 = h1b / (1.0f + __expf(-h1b)) * acc[i][j + 4][1];
                float o2 = h1c / (1.0f + __expf(-h1c)) * acc[i][j + 4][2];
                float o3 = h1d / (1.0f + __expf(-h1d)) * acc[i][j + 4][3];
                *(__half2*)(ACT + (size_t)r * F_DIM + c) = __floats2half2_rn(o0, o1);
                *(__half2*)(ACT + (size_t)(r + 8) * F_DIM + c) = __floats2half2_rn(o2, o3);
            }
        }
    } else {
        float* dst = outP + (size_t)sp * ((size_t)T_TOK * H_DIM);
        #pragma unroll
        for (int i = 0; i < 4; i++) {
            #pragma unroll
            for (int j = 0; j < 8; j++) {
                int r = r0 + i * 16;
                int c = n0 + wn * 64 + j * 8 + (lane & 3) * 2;
                float2 lo = { acc[i][j][0], acc[i][j][1] };
                float2 hi = { acc[i][j][2], acc[i][j][3] };
                *(float2*)(dst + (size_t)r * H_DIM + c) = lo;
                *(float2*)(dst + (size_t)(r + 8) * H_DIM + c) = hi;
            }
        }
    }
#undef LOADW
#undef LOADA
}

// ================= split-K reduce (7 partials) =================
__global__ void reduce7_kernel(float* __restrict__ out) {
    const size_t S = (size_t)T_TOK * H_DIM / 4;
    size_t i = (size_t)blockIdx.x * blockDim.x + threadIdx.x;
    const float4* p = (const float4*)g_P2;
    float4 r = p[i];
    #pragma unroll
    for (int s = 1; s < SPLIT; s++) {
        float4 v = p[i + (size_t)s * S];
        r.x += v.x; r.y += v.y; r.z += v.z; r.w += v.w;
    }
    ((float4*)out)[i] = r;
}

// ================= launch =================
extern "C" void kernel_launch(void* const* d_in, const int* in_sizes, int n_in,
                              void* d_out, int out_size) {
    const float* x  = (const float*)d_in[0];
    const int* W1q  = (const int*)d_in[1];
    const float* s1 = (const float*)d_in[2];
    const float* z1 = (const float*)d_in[3];
    const int* W3q  = (const int*)d_in[4];
    const float* s3 = (const float*)d_in[5];
    const float* z3 = (const float*)d_in[6];
    const int* W2q  = (const int*)d_in[7];
    const float* s2 = (const float*)d_in[8];
    const float* z2 = (const float*)d_in[9];
    float* out = (float*)d_out;

    void *pXh, *pACT, *pP2;
    cudaGetSymbolAddress(&pXh, g_Xh);
    cudaGetSymbolAddress(&pACT, g_ACT);
    cudaGetSymbolAddress(&pP2, g_P2);
    const __half* Xh = (const __half*)pXh;
    __half* ACT = (__half*)pACT;
    float* P2 = (float*)pP2;

    cudaFuncSetAttribute(tc_gemm<0>, cudaFuncAttributeMaxDynamicSharedMemorySize, SMEM_TOTAL);
    cudaFuncSetAttribute(tc_gemm<1>, cudaFuncAttributeMaxDynamicSharedMemorySize, SMEM_TOTAL);

    convert_x_kernel<<<(T_TOK * H_DIM) / 1024, 1024>>>(x);

    // fused G1+G3 -> ACT : grid (m fastest for L2 weight sharing)
    tc_gemm<0><<<dim3(T_TOK / M_TILE, F_DIM / 64), THREADS, SMEM_TOTAL>>>(
        Xh, W1q, W3q, s1, z1, s3, z3, H_DIM, H_DIM / KC, ACT, nullptr);

    // G2 split-K=7 : grid (14 = 2 m-tiles x 7 splits, 32 n-tiles)
    tc_gemm<1><<<dim3(2 * SPLIT, H_DIM / 128), THREADS, SMEM_TOTAL>>>(
        ACT, W2q, W2q, s2, z2, s2, z2, F_DIM, F_DIM / (KC * SPLIT), nullptr, P2);

    reduce7_kernel<<<(T_TOK * H_DIM / 4) / 256, 256>>>(out);
}